// round 12
// baseline (speedup 1.0000x reference)
#include <cuda_runtime.h>

// 2-layer GRU (PyTorch semantics) + linear head. T=512, B=4096, I=2, H=64.
// 148 persistent blocks x 512 threads (all SMs), 28 batch rows/block (padded
// 4144; x clamped, out predicated). 2 independent 256-thread groups of 14
// rows, 1 group-barrier/step. Warps 0-3 of a group: 8-row region; 4-7: 6-row.
// THIS ROUND: slot-interleaved h array hx[k][region][q][src] (256B per k).
// In the layer-1 GEMM the ks0 lane-half reads the h0 chunk and ks1 the h1
// chunk of the SAME 128B window -> 1 wavefront per h LDS.128. Layer-0 pairs
// (h0[i], h0[i+16]) -> 2 aligned windows (no straddle). Instruction counts
// identical to R11 -- pure layout experiment.

#define TT   512
#define BB   4096
#define NBLK 148
#define NTHR 512

typedef unsigned long long u64;

// SMEM (floats):
//  w0 [32 kp][384]: per kp: RZ (64 j x {R u64, Z u64}) + N (64 j x u64) @+256
//  w1 [64 kp][384]: kp<32 = Wih1, kp>=32 = Whh1
//  hx @36864, per group 4096: 2 bufs x (32 k x 64 fl)
//     addr(k,bg,q,src,rlo,e) = k*64 + bg*32 + q*8 + src*4 + rlo*2 + e
//     (src0 = h0, src1 = h1; B8 region q 0..3, B6 region q 0..2 + pad)
#define OFF_W0 0
#define OFF_W1 12288
#define OFF_H  36864
#define GRPH   4096
#define SMEM_FLOATS (OFF_H + 2*GRPH)     // 45056
#define SMEM_BYTES  (SMEM_FLOATS * 4)    // 180224

__device__ __forceinline__ void ffma2(u64& d, u64 a, u64 b) {
    asm("fma.rn.f32x2 %0, %1, %2, %0;" : "+l"(d) : "l"(a), "l"(b));
}
__device__ __forceinline__ void fadd2(u64& d, u64 a) {
    asm("add.rn.f32x2 %0, %0, %1;" : "+l"(d) : "l"(a));
}
__device__ __forceinline__ float fold(u64 v) {
    float lo, hi;
    asm("mov.b64 {%0,%1}, %2;" : "=f"(lo), "=f"(hi) : "l"(v));
    return lo + hi;
}
__device__ __forceinline__ float tanh_(float x) {
    float r; asm("tanh.approx.f32 %0, %1;" : "=f"(r) : "f"(x)); return r;
}
__device__ __forceinline__ float sigm(float x) {
    return fmaf(tanh_(0.5f * x), 0.5f, 0.5f);
}

#define GRPBAR256(id) asm volatile("bar.sync %0, 256;" :: "r"(id) : "memory")

// GEMM over NKP k's, NB rows. wrz = base + j*4 (stride 384), wn = +256+j*2.
// hb = hx base + region/slot offsets; per-k stride 64 floats, chunks at q*8.
template<int NKP, int NB>
__device__ __forceinline__ void gemm_rzn(const float* __restrict__ wrz,
                                         const float* __restrict__ wn,
                                         const float* __restrict__ hb,
                                         u64 aR[NB], u64 aZ[NB], u64 aN[NB])
{
    #pragma unroll 4
    for (int kp = 0; kp < NKP; ++kp) {
        ulonglong2 wv = *(const ulonglong2*)(wrz + kp * 384);
        u64 wNv = *(const u64*)(wn + kp * 384);
        const float* hr = hb + kp * 64;
        u64 hv[NB];
        {
            ulonglong2 t0 = *(const ulonglong2*)(hr);
            ulonglong2 t1 = *(const ulonglong2*)(hr + 8);
            hv[0] = t0.x; hv[1] = t0.y; hv[2] = t1.x; hv[3] = t1.y;
            if constexpr (NB == 8) {
                ulonglong2 t2 = *(const ulonglong2*)(hr + 16);
                ulonglong2 t3 = *(const ulonglong2*)(hr + 24);
                hv[4] = t2.x; hv[5] = t2.y; hv[6] = t3.x; hv[7] = t3.y;
            } else {
                ulonglong2 t2 = *(const ulonglong2*)(hr + 16);
                hv[4] = t2.x; hv[5] = t2.y;
            }
        }
        #pragma unroll
        for (int b = 0; b < NB; ++b) {
            ffma2(aR[b], hv[b], wv.x);
            ffma2(aZ[b], hv[b], wv.y);
            ffma2(aN[b], hv[b], wNv);
        }
    }
}

struct Ctx {
    const float* gx;
    float* hx;                         // group hx base (2 bufs x 2048)
    const float* w0rz; const float* w0n;
    const float* w1rz; const float* w1n;
    int ks, bgf, stE, bglob, bar_id;
    float wxr0, wxr1, wxz0, wxz1, wxn0, wxn1;
    float br0, bz0, bnx0, bnh0, br1, bz1, bnx1, bnh1;
};

template<int NB>
__device__ __forceinline__ void time_loop(const Ctx c, float* hprev0, float* hprev1)
{
    constexpr int F = NB / 2;
    const int ks = c.ks;
    // per-ii store offsets (t-invariant): row r = ks*F + ii within region
    int soff[F];
    #pragma unroll
    for (int ii = 0; ii < F; ++ii) {
        int r = ks * F + ii;
        soff[ii] = c.stE + (r >> 1) * 8 + (r & 1) * 2;
    }

    for (int t = 0; t < TT; ++t) {
        const int cur = t & 1;
        float* hxc = c.hx + cur * 2048;          // E0 writes h0(t); G1 reads
        float* hxn = c.hx + (cur ^ 1) * 2048;    // G0 reads h0(t-1); E1 writes h1(t)

        // x(t) for my F finalized rows (clamped for padded tail rows)
        float xf[2 * F];
        #pragma unroll
        for (int i = 0; i < F; ++i) {
            int br = c.bglob + i; if (br > BB - 1) br = BB - 1;
            float2 v = *(const float2*)(c.gx + ((size_t)t * BB + br) * 2);
            xf[2 * i] = v.x; xf[2 * i + 1] = v.y;
        }

        // ======== G0: layer-0 GEMM, my k-half over h0(t-1) (src0 slots) ========
        u64 aR[NB], aZ[NB], aN[NB];
        #pragma unroll
        for (int b = 0; b < NB; ++b) { aR[b] = 0; aZ[b] = 0; aN[b] = 0; }
        gemm_rzn<16, NB>(c.w0rz, c.w0n, hxn + ks * 1024 + c.bgf, aR, aZ, aN);

        // ======== E0: k-split reduce + gates; write h0(t) -> hxc src0 ========
        #pragma unroll
        for (int i = 0; i < F; ++i) {
            u64 keepR = ks ? aR[F+i] : aR[i], sndR = ks ? aR[i] : aR[F+i];
            u64 keepZ = ks ? aZ[F+i] : aZ[i], sndZ = ks ? aZ[i] : aZ[F+i];
            u64 keepN = ks ? aN[F+i] : aN[i], sndN = ks ? aN[i] : aN[F+i];
            fadd2(keepR, __shfl_xor_sync(0xffffffffu, sndR, 16));
            fadd2(keepZ, __shfl_xor_sync(0xffffffffu, sndZ, 16));
            fadd2(keepN, __shfl_xor_sync(0xffffffffu, sndN, 16));
            float sR = fold(keepR), sZ = fold(keepZ), sN = fold(keepN);
            float x0 = xf[2*i], x1 = xf[2*i+1];
            float r = sigm(sR + x0 * c.wxr0 + x1 * c.wxr1 + c.br0);
            float z = sigm(sZ + x0 * c.wxz0 + x1 * c.wxz1 + c.bz0);
            float n = tanh_(x0 * c.wxn0 + x1 * c.wxn1 + c.bnx0 + r * (sN + c.bnh0));
            float h = n + z * (hprev0[i] - n);
            hprev0[i] = h;
            hxc[soff[i]] = h;                    // src0 slot
        }
        GRPBAR256(c.bar_id);   // h0(t) visible within group (only bar this step)

        // ==== G1: layer-1 GEMM over hxc. ks0 lanes read src0 chunks (fresh h0),
        //      ks1 lanes read src1 chunks (h1(t-1)) — SAME 128B window: 1 wf. ====
        u64 cR[NB], cZ[NB], cN[NB];
        #pragma unroll
        for (int b = 0; b < NB; ++b) { cR[b] = 0; cZ[b] = 0; cN[b] = 0; }
        gemm_rzn<32, NB>(c.w1rz, c.w1n, hxc + c.bgf + ks * 4, cR, cZ, cN);

        // ======== E1: exchange + gates; write h1(t) -> hxn src1 ========
        #pragma unroll
        for (int i = 0; i < F; ++i) {
            u64 keepR = ks ? cR[F+i] : cR[i], sndR = ks ? cR[i] : cR[F+i];
            u64 keepZ = ks ? cZ[F+i] : cZ[i], sndZ = ks ? cZ[i] : cZ[F+i];
            u64 keepN = ks ? cN[F+i] : cN[i], sndN = ks ? cN[i] : cN[F+i];
            fadd2(keepR, __shfl_xor_sync(0xffffffffu, sndR, 16));
            fadd2(keepZ, __shfl_xor_sync(0xffffffffu, sndZ, 16));
            u64 rcvN = __shfl_xor_sync(0xffffffffu, sndN, 16);
            float sR = fold(keepR), sZ = fold(keepZ);
            float fm = fold(keepN), fr = fold(rcvN);
            float nx = ks ? fr : fm;      // input-side partial came from ks0
            float nh = ks ? fm : fr;      // recurrent partial came from ks1
            float r = sigm(sR + c.br1);
            float z = sigm(sZ + c.bz1);
            float n = tanh_(nx + c.bnx1 + r * (nh + c.bnh1));
            float h = n + z * (hprev1[i] - n);
            hprev1[i] = h;
            hxn[soff[i] + 4] = h;                // src1 slot
        }
        // Single-barrier safety: passing bar(t) requires every group thread
        // completed G1(t-1), E1(t-1), G0(t), E0(t). E1(t)'s writes target only
        // src1 slots, disjoint from G0's src0 reads in the same buffer.
    }
}

extern "C" __global__ void __launch_bounds__(NTHR, 1)
gru2_kernel(const float* __restrict__ gx,
            const float* __restrict__ Wih0, const float* __restrict__ Whh0,
            const float* __restrict__ bih0, const float* __restrict__ bhh0,
            const float* __restrict__ Wih1, const float* __restrict__ Whh1,
            const float* __restrict__ bih1, const float* __restrict__ bhh1,
            const float* __restrict__ Wp,   const float* __restrict__ bp,
            float* __restrict__ out)
{
    extern __shared__ __align__(16) float sm[];
    const int tid = threadIdx.x;

    // ---- one-time weight staging (R6/R11 layout) ----
    for (int i = tid; i < 12288; i += NTHR) {
        int kp = i / 384, r = i % 384;
        float v;
        if (r < 256) {
            int j = r >> 2, sub = r & 3, gate = sub >> 1, e = sub & 1;
            v = Whh0[(gate * 64 + j) * 64 + 2 * kp + e];
        } else {
            int rr = r - 256, j = rr >> 1, e = rr & 1;
            v = Whh0[(128 + j) * 64 + 2 * kp + e];
        }
        sm[OFF_W0 + i] = v;
    }
    for (int i = tid; i < 24576; i += NTHR) {
        int kp = i / 384, r = i % 384;
        const float* W = (kp < 32) ? Wih1 : Whh1;
        int k0 = 2 * (kp & 31);
        float v;
        if (r < 256) {
            int j = r >> 2, sub = r & 3, gate = sub >> 1, e = sub & 1;
            v = W[(gate * 64 + j) * 64 + k0 + e];
        } else {
            int rr = r - 256, j = rr >> 1, e = rr & 1;
            v = W[(128 + j) * 64 + k0 + e];
        }
        sm[OFF_W1 + i] = v;
    }
    for (int i = tid; i < 2 * GRPH; i += NTHR) sm[OFF_H + i] = 0.0f;

    // ---- per-thread mapping ----
    const int warp   = tid >> 5;
    const int g      = tid >> 8;            // group 0/1 (warps 0-7 | 8-15)
    const int warp_g = warp & 7;
    const int jw     = warp_g & 3;          // 4 j-warps cover 64 j
    const int bg     = warp_g >> 2;         // region: 0 = 8 rows, 1 = 6 rows
    const int lane   = tid & 31;
    const int ks     = lane >> 4;
    const int jq     = lane & 15;
    const int j      = jw * 16 + jq;        // my j column (0..63)
    const int kpj    = j >> 1, ej = j & 1;
    const int F      = bg ? 3 : 4;
    const int lrow0  = bg * 8 + ks * F;     // first finalized local row (of 14)
    const int bglob  = blockIdx.x * 28 + g * 14 + lrow0;

    Ctx c;
    c.gx = gx;
    c.ks = ks;
    c.bgf = bg * 32;
    c.stE = kpj * 64 + bg * 32 + ej;        // + (r>>1)*8 + (r&1)*2 (+4 for h1)
    c.bglob = bglob;
    c.bar_id = g + 1;

    c.wxr0 = Wih0[j*2];        c.wxr1 = Wih0[j*2+1];
    c.wxz0 = Wih0[(64+j)*2];   c.wxz1 = Wih0[(64+j)*2+1];
    c.wxn0 = Wih0[(128+j)*2];  c.wxn1 = Wih0[(128+j)*2+1];
    c.br0 = bih0[j]    + bhh0[j];
    c.bz0 = bih0[64+j] + bhh0[64+j];
    c.bnx0 = bih0[128+j]; c.bnh0 = bhh0[128+j];
    c.br1 = bih1[j]    + bhh1[j];
    c.bz1 = bih1[64+j] + bhh1[64+j];
    c.bnx1 = bih1[128+j]; c.bnh1 = bhh1[128+j];

    c.w0rz = sm + OFF_W0 + (ks * 16) * 384 + j * 4;
    c.w0n  = sm + OFF_W0 + (ks * 16) * 384 + 256 + j * 2;
    c.w1rz = sm + OFF_W1 + (ks * 32) * 384 + j * 4;   // ks0: Wih1, ks1: Whh1
    c.w1n  = sm + OFF_W1 + (ks * 32) * 384 + 256 + j * 2;

    c.hx = sm + OFF_H + g * GRPH;           // 2 bufs x 2048

    float hprev0[4] = {0.f, 0.f, 0.f, 0.f};
    float hprev1[4] = {0.f, 0.f, 0.f, 0.f};

    __syncthreads();

    if (bg == 0) time_loop<8>(c, hprev0, hprev1);
    else         time_loop<6>(c, hprev0, hprev1);

    // ---- projection: out[b] = sum_j Wp[j]*h0f[j] + Wp[64+j]*h1f[j] + bp ----
    __syncthreads();   // all groups done with h buffers
    {
        float* scr = sm + OFF_H;   // [28 rows][stride 68]
        const float wp0 = Wp[j], wp1 = Wp[64 + j];
        #pragma unroll
        for (int i = 0; i < 4; ++i) {
            if (i < F) {
                int lr = g * 14 + lrow0 + i;
                scr[lr * 68 + j] = wp0 * hprev0[i] + wp1 * hprev1[i];
            }
        }
        __syncthreads();
        if (tid < 28) {
            int rowg = blockIdx.x * 28 + tid;
            if (rowg < BB) {
                float s = bp[0];
                #pragma unroll 8
                for (int jj = 0; jj < 64; ++jj) s += scr[tid * 68 + jj];
                out[rowg] = s;
            }
        }
    }
}

extern "C" void kernel_launch(void* const* d_in, const int* in_sizes, int n_in,
                              void* d_out, int out_size)
{
    (void)in_sizes; (void)n_in; (void)out_size;
    const float* x    = (const float*)d_in[0];
    const float* Wih0 = (const float*)d_in[1];
    const float* Whh0 = (const float*)d_in[2];
    const float* bih0 = (const float*)d_in[3];
    const float* bhh0 = (const float*)d_in[4];
    const float* Wih1 = (const float*)d_in[5];
    const float* Whh1 = (const float*)d_in[6];
    const float* bih1 = (const float*)d_in[7];
    const float* bhh1 = (const float*)d_in[8];
    const float* Wp   = (const float*)d_in[9];
    const float* bp   = (const float*)d_in[10];
    float* out = (float*)d_out;

    cudaFuncSetAttribute(gru2_kernel, cudaFuncAttributeMaxDynamicSharedMemorySize, SMEM_BYTES);
    gru2_kernel<<<NBLK, NTHR, SMEM_BYTES>>>(x, Wih0, Whh0, bih0, bhh0,
                                            Wih1, Whh1, bih1, bhh1, Wp, bp, out);
}

// round 13
// speedup vs baseline: 1.0021x; 1.0021x over previous
#include <cuda_runtime.h>

// 2-layer GRU (PyTorch semantics) + linear head. T=512, B=4096, I=2, H=64.
// 148 persistent blocks x 512 threads (all SMs), 28 batch rows/block (padded
// 4144; x clamped, out predicated). 2 independent 256-thread groups of 14
// rows, 1 group-barrier/step. Warps 0-3 of a group: 8-row region; 4-7: 6-row.
// THIS ROUND: slot-interleaved h array hx[k][region][q][src] (256B per k).
// In the layer-1 GEMM the ks0 lane-half reads the h0 chunk and ks1 the h1
// chunk of the SAME 128B window -> 1 wavefront per h LDS.128. Layer-0 pairs
// (h0[i], h0[i+16]) -> 2 aligned windows (no straddle). Instruction counts
// identical to R11 -- pure layout experiment.

#define TT   512
#define BB   4096
#define NBLK 148
#define NTHR 512

typedef unsigned long long u64;

// SMEM (floats):
//  w0 [32 kp][384]: per kp: RZ (64 j x {R u64, Z u64}) + N (64 j x u64) @+256
//  w1 [64 kp][384]: kp<32 = Wih1, kp>=32 = Whh1
//  hx @36864, per group 4096: 2 bufs x (32 k x 64 fl)
//     addr(k,bg,q,src,rlo,e) = k*64 + bg*32 + q*8 + src*4 + rlo*2 + e
//     (src0 = h0, src1 = h1; B8 region q 0..3, B6 region q 0..2 + pad)
#define OFF_W0 0
#define OFF_W1 12288
#define OFF_H  36864
#define GRPH   4096
#define SMEM_FLOATS (OFF_H + 2*GRPH)     // 45056
#define SMEM_BYTES  (SMEM_FLOATS * 4)    // 180224

__device__ __forceinline__ void ffma2(u64& d, u64 a, u64 b) {
    asm("fma.rn.f32x2 %0, %1, %2, %0;" : "+l"(d) : "l"(a), "l"(b));
}
__device__ __forceinline__ void fadd2(u64& d, u64 a) {
    asm("add.rn.f32x2 %0, %0, %1;" : "+l"(d) : "l"(a));
}
__device__ __forceinline__ float fold(u64 v) {
    float lo, hi;
    asm("mov.b64 {%0,%1}, %2;" : "=f"(lo), "=f"(hi) : "l"(v));
    return lo + hi;
}
__device__ __forceinline__ float tanh_(float x) {
    float r; asm("tanh.approx.f32 %0, %1;" : "=f"(r) : "f"(x)); return r;
}
__device__ __forceinline__ float sigm(float x) {
    return fmaf(tanh_(0.5f * x), 0.5f, 0.5f);
}

#define GRPBAR256(id) asm volatile("bar.sync %0, 256;" :: "r"(id) : "memory")

// GEMM over NKP k's, NB rows. wrz = base + j*4 (stride 384), wn = +256+j*2.
// hb = hx base + region/slot offsets; per-k stride 64 floats, chunks at q*8.
template<int NKP, int NB>
__device__ __forceinline__ void gemm_rzn(const float* __restrict__ wrz,
                                         const float* __restrict__ wn,
                                         const float* __restrict__ hb,
                                         u64 aR[NB], u64 aZ[NB], u64 aN[NB])
{
    #pragma unroll 4
    for (int kp = 0; kp < NKP; ++kp) {
        ulonglong2 wv = *(const ulonglong2*)(wrz + kp * 384);
        u64 wNv = *(const u64*)(wn + kp * 384);
        const float* hr = hb + kp * 64;
        u64 hv[NB];
        {
            ulonglong2 t0 = *(const ulonglong2*)(hr);
            ulonglong2 t1 = *(const ulonglong2*)(hr + 8);
            hv[0] = t0.x; hv[1] = t0.y; hv[2] = t1.x; hv[3] = t1.y;
            if constexpr (NB == 8) {
                ulonglong2 t2 = *(const ulonglong2*)(hr + 16);
                ulonglong2 t3 = *(const ulonglong2*)(hr + 24);
                hv[4] = t2.x; hv[5] = t2.y; hv[6] = t3.x; hv[7] = t3.y;
            } else {
                ulonglong2 t2 = *(const ulonglong2*)(hr + 16);
                hv[4] = t2.x; hv[5] = t2.y;
            }
        }
        #pragma unroll
        for (int b = 0; b < NB; ++b) {
            ffma2(aR[b], hv[b], wv.x);
            ffma2(aZ[b], hv[b], wv.y);
            ffma2(aN[b], hv[b], wNv);
        }
    }
}

struct Ctx {
    const float* gx;
    float* hx;                         // group hx base (2 bufs x 2048)
    const float* w0rz; const float* w0n;
    const float* w1rz; const float* w1n;
    int ks, bgf, stE, bglob, bar_id;
    float wxr0, wxr1, wxz0, wxz1, wxn0, wxn1;
    float br0, bz0, bnx0, bnh0, br1, bz1, bnx1, bnh1;
};

template<int NB>
__device__ __forceinline__ void time_loop(const Ctx c, float* hprev0, float* hprev1)
{
    constexpr int F = NB / 2;
    const int ks = c.ks;
    // per-ii store offsets (t-invariant): row r = ks*F + ii within region
    int soff[F];
    #pragma unroll
    for (int ii = 0; ii < F; ++ii) {
        int r = ks * F + ii;
        soff[ii] = c.stE + (r >> 1) * 8 + (r & 1) * 2;
    }

    for (int t = 0; t < TT; ++t) {
        const int cur = t & 1;
        float* hxc = c.hx + cur * 2048;          // E0 writes h0(t); G1 reads
        float* hxn = c.hx + (cur ^ 1) * 2048;    // G0 reads h0(t-1); E1 writes h1(t)

        // x(t) for my F finalized rows (clamped for padded tail rows)
        float xf[2 * F];
        #pragma unroll
        for (int i = 0; i < F; ++i) {
            int br = c.bglob + i; if (br > BB - 1) br = BB - 1;
            float2 v = *(const float2*)(c.gx + ((size_t)t * BB + br) * 2);
            xf[2 * i] = v.x; xf[2 * i + 1] = v.y;
        }

        // ======== G0: layer-0 GEMM, my k-half over h0(t-1) (src0 slots) ========
        u64 aR[NB], aZ[NB], aN[NB];
        #pragma unroll
        for (int b = 0; b < NB; ++b) { aR[b] = 0; aZ[b] = 0; aN[b] = 0; }
        gemm_rzn<16, NB>(c.w0rz, c.w0n, hxn + ks * 1024 + c.bgf, aR, aZ, aN);

        // ======== E0: k-split reduce + gates; write h0(t) -> hxc src0 ========
        #pragma unroll
        for (int i = 0; i < F; ++i) {
            u64 keepR = ks ? aR[F+i] : aR[i], sndR = ks ? aR[i] : aR[F+i];
            u64 keepZ = ks ? aZ[F+i] : aZ[i], sndZ = ks ? aZ[i] : aZ[F+i];
            u64 keepN = ks ? aN[F+i] : aN[i], sndN = ks ? aN[i] : aN[F+i];
            fadd2(keepR, __shfl_xor_sync(0xffffffffu, sndR, 16));
            fadd2(keepZ, __shfl_xor_sync(0xffffffffu, sndZ, 16));
            fadd2(keepN, __shfl_xor_sync(0xffffffffu, sndN, 16));
            float sR = fold(keepR), sZ = fold(keepZ), sN = fold(keepN);
            float x0 = xf[2*i], x1 = xf[2*i+1];
            float r = sigm(sR + x0 * c.wxr0 + x1 * c.wxr1 + c.br0);
            float z = sigm(sZ + x0 * c.wxz0 + x1 * c.wxz1 + c.bz0);
            float n = tanh_(x0 * c.wxn0 + x1 * c.wxn1 + c.bnx0 + r * (sN + c.bnh0));
            float h = n + z * (hprev0[i] - n);
            hprev0[i] = h;
            hxc[soff[i]] = h;                    // src0 slot
        }
        GRPBAR256(c.bar_id);   // h0(t) visible within group (only bar this step)

        // ==== G1: layer-1 GEMM over hxc. ks0 lanes read src0 chunks (fresh h0),
        //      ks1 lanes read src1 chunks (h1(t-1)) — SAME 128B window: 1 wf. ====
        u64 cR[NB], cZ[NB], cN[NB];
        #pragma unroll
        for (int b = 0; b < NB; ++b) { cR[b] = 0; cZ[b] = 0; cN[b] = 0; }
        gemm_rzn<32, NB>(c.w1rz, c.w1n, hxc + c.bgf + ks * 4, cR, cZ, cN);

        // ======== E1: exchange + gates; write h1(t) -> hxn src1 ========
        #pragma unroll
        for (int i = 0; i < F; ++i) {
            u64 keepR = ks ? cR[F+i] : cR[i], sndR = ks ? cR[i] : cR[F+i];
            u64 keepZ = ks ? cZ[F+i] : cZ[i], sndZ = ks ? cZ[i] : cZ[F+i];
            u64 keepN = ks ? cN[F+i] : cN[i], sndN = ks ? cN[i] : cN[F+i];
            fadd2(keepR, __shfl_xor_sync(0xffffffffu, sndR, 16));
            fadd2(keepZ, __shfl_xor_sync(0xffffffffu, sndZ, 16));
            u64 rcvN = __shfl_xor_sync(0xffffffffu, sndN, 16);
            float sR = fold(keepR), sZ = fold(keepZ);
            float fm = fold(keepN), fr = fold(rcvN);
            float nx = ks ? fr : fm;      // input-side partial came from ks0
            float nh = ks ? fm : fr;      // recurrent partial came from ks1
            float r = sigm(sR + c.br1);
            float z = sigm(sZ + c.bz1);
            float n = tanh_(nx + c.bnx1 + r * (nh + c.bnh1));
            float h = n + z * (hprev1[i] - n);
            hprev1[i] = h;
            hxn[soff[i] + 4] = h;                // src1 slot
        }
        // Single-barrier safety: passing bar(t) requires every group thread
        // completed G1(t-1), E1(t-1), G0(t), E0(t). E1(t)'s writes target only
        // src1 slots, disjoint from G0's src0 reads in the same buffer.
    }
}

extern "C" __global__ void __launch_bounds__(NTHR, 1)
gru2_kernel(const float* __restrict__ gx,
            const float* __restrict__ Wih0, const float* __restrict__ Whh0,
            const float* __restrict__ bih0, const float* __restrict__ bhh0,
            const float* __restrict__ Wih1, const float* __restrict__ Whh1,
            const float* __restrict__ bih1, const float* __restrict__ bhh1,
            const float* __restrict__ Wp,   const float* __restrict__ bp,
            float* __restrict__ out)
{
    extern __shared__ __align__(16) float sm[];
    const int tid = threadIdx.x;

    // ---- one-time weight staging (R6/R11 layout) ----
    for (int i = tid; i < 12288; i += NTHR) {
        int kp = i / 384, r = i % 384;
        float v;
        if (r < 256) {
            int j = r >> 2, sub = r & 3, gate = sub >> 1, e = sub & 1;
            v = Whh0[(gate * 64 + j) * 64 + 2 * kp + e];
        } else {
            int rr = r - 256, j = rr >> 1, e = rr & 1;
            v = Whh0[(128 + j) * 64 + 2 * kp + e];
        }
        sm[OFF_W0 + i] = v;
    }
    for (int i = tid; i < 24576; i += NTHR) {
        int kp = i / 384, r = i % 384;
        const float* W = (kp < 32) ? Wih1 : Whh1;
        int k0 = 2 * (kp & 31);
        float v;
        if (r < 256) {
            int j = r >> 2, sub = r & 3, gate = sub >> 1, e = sub & 1;
            v = W[(gate * 64 + j) * 64 + k0 + e];
        } else {
            int rr = r - 256, j = rr >> 1, e = rr & 1;
            v = W[(128 + j) * 64 + k0 + e];
        }
        sm[OFF_W1 + i] = v;
    }
    for (int i = tid; i < 2 * GRPH; i += NTHR) sm[OFF_H + i] = 0.0f;

    // ---- per-thread mapping ----
    const int warp   = tid >> 5;
    const int g      = tid >> 8;            // group 0/1 (warps 0-7 | 8-15)
    const int warp_g = warp & 7;
    const int jw     = warp_g & 3;          // 4 j-warps cover 64 j
    const int bg     = warp_g >> 2;         // region: 0 = 8 rows, 1 = 6 rows
    const int lane   = tid & 31;
    const int ks     = lane >> 4;
    const int jq     = lane & 15;
    const int j      = jw * 16 + jq;        // my j column (0..63)
    const int kpj    = j >> 1, ej = j & 1;
    const int F      = bg ? 3 : 4;
    const int lrow0  = bg * 8 + ks * F;     // first finalized local row (of 14)
    const int bglob  = blockIdx.x * 28 + g * 14 + lrow0;

    Ctx c;
    c.gx = gx;
    c.ks = ks;
    c.bgf = bg * 32;
    c.stE = kpj * 64 + bg * 32 + ej;        // + (r>>1)*8 + (r&1)*2 (+4 for h1)
    c.bglob = bglob;
    c.bar_id = g + 1;

    c.wxr0 = Wih0[j*2];        c.wxr1 = Wih0[j*2+1];
    c.wxz0 = Wih0[(64+j)*2];   c.wxz1 = Wih0[(64+j)*2+1];
    c.wxn0 = Wih0[(128+j)*2];  c.wxn1 = Wih0[(128+j)*2+1];
    c.br0 = bih0[j]    + bhh0[j];
    c.bz0 = bih0[64+j] + bhh0[64+j];
    c.bnx0 = bih0[128+j]; c.bnh0 = bhh0[128+j];
    c.br1 = bih1[j]    + bhh1[j];
    c.bz1 = bih1[64+j] + bhh1[64+j];
    c.bnx1 = bih1[128+j]; c.bnh1 = bhh1[128+j];

    c.w0rz = sm + OFF_W0 + (ks * 16) * 384 + j * 4;
    c.w0n  = sm + OFF_W0 + (ks * 16) * 384 + 256 + j * 2;
    c.w1rz = sm + OFF_W1 + (ks * 32) * 384 + j * 4;   // ks0: Wih1, ks1: Whh1
    c.w1n  = sm + OFF_W1 + (ks * 32) * 384 + 256 + j * 2;

    c.hx = sm + OFF_H + g * GRPH;           // 2 bufs x 2048

    float hprev0[4] = {0.f, 0.f, 0.f, 0.f};
    float hprev1[4] = {0.f, 0.f, 0.f, 0.f};

    __syncthreads();

    if (bg == 0) time_loop<8>(c, hprev0, hprev1);
    else         time_loop<6>(c, hprev0, hprev1);

    // ---- projection: out[b] = sum_j Wp[j]*h0f[j] + Wp[64+j]*h1f[j] + bp ----
    __syncthreads();   // all groups done with h buffers
    {
        float* scr = sm + OFF_H;   // [28 rows][stride 68]
        const float wp0 = Wp[j], wp1 = Wp[64 + j];
        #pragma unroll
        for (int i = 0; i < 4; ++i) {
            if (i < F) {
                int lr = g * 14 + lrow0 + i;
                scr[lr * 68 + j] = wp0 * hprev0[i] + wp1 * hprev1[i];
            }
        }
        __syncthreads();
        if (tid < 28) {
            int rowg = blockIdx.x * 28 + tid;
            if (rowg < BB) {
                float s = bp[0];
                #pragma unroll 8
                for (int jj = 0; jj < 64; ++jj) s += scr[tid * 68 + jj];
                out[rowg] = s;
            }
        }
    }
}

extern "C" void kernel_launch(void* const* d_in, const int* in_sizes, int n_in,
                              void* d_out, int out_size)
{
    (void)in_sizes; (void)n_in; (void)out_size;
    const float* x    = (const float*)d_in[0];
    const float* Wih0 = (const float*)d_in[1];
    const float* Whh0 = (const float*)d_in[2];
    const float* bih0 = (const float*)d_in[3];
    const float* bhh0 = (const float*)d_in[4];
    const float* Wih1 = (const float*)d_in[5];
    const float* Whh1 = (const float*)d_in[6];
    const float* bih1 = (const float*)d_in[7];
    const float* bhh1 = (const float*)d_in[8];
    const float* Wp   = (const float*)d_in[9];
    const float* bp   = (const float*)d_in[10];
    float* out = (float*)d_out;

    cudaFuncSetAttribute(gru2_kernel, cudaFuncAttributeMaxDynamicSharedMemorySize, SMEM_BYTES);
    gru2_kernel<<<NBLK, NTHR, SMEM_BYTES>>>(x, Wih0, Whh0, bih0, bhh0,
                                            Wih1, Whh1, bih1, bhh1, Wp, bp, out);
}

// round 14
// speedup vs baseline: 1.0892x; 1.0869x over previous
#include <cuda_runtime.h>

// 2-layer GRU (PyTorch semantics) + linear head. T=512, B=4096, I=2, H=64.
// 148 persistent blocks x 512 threads (all SMs), 28 batch rows/block (padded
// 4144; x clamped, out predicated). 2 independent 256-thread groups of 14
// rows, 1 group-barrier/step. Warps 0-3 of a group: 8-row region; 4-7: 6-row.
// R13 = R11 (best) + fully-unrolled GEMM loops (immediate-offset operands,
// less ALU) + t-invariant clamped x pointers hoisted out of the time loop.
// Per-thread: 1 j x NB rows GEMM, in-warp k-split (lane bit 4), f32x2 packs
// (even-k, odd-k); k-split reduced by shfl.bfly(16); NB/2 rows finalized.

#define TT   512
#define BB   4096
#define NBLK 148
#define NTHR 512

typedef unsigned long long u64;

// SMEM (floats):
//  w0 [32 kp][384]: per kp: RZ (64 j x {R u64, Z u64}) + N (64 j x u64) @+256
//  w1 [64 kp][384]: kp<32 = Wih1, kp>=32 = Whh1
//  h  @36864, per group 3584: hp0 2 bufs x 896, hp1 2 bufs x 896
//     row layout per kp: 28 floats = [bg0: 8 rows x2][bg1: 6 rows x2]
#define OFF_W0 0
#define OFF_W1 12288
#define OFF_H  36864
#define GRPH   3584
#define SMEM_FLOATS (OFF_H + 2*GRPH)     // 44032
#define SMEM_BYTES  (SMEM_FLOATS * 4)    // 176128

__device__ __forceinline__ void ffma2(u64& d, u64 a, u64 b) {
    asm("fma.rn.f32x2 %0, %1, %2, %0;" : "+l"(d) : "l"(a), "l"(b));
}
__device__ __forceinline__ void fadd2(u64& d, u64 a) {
    asm("add.rn.f32x2 %0, %0, %1;" : "+l"(d) : "l"(a));
}
__device__ __forceinline__ float fold(u64 v) {
    float lo, hi;
    asm("mov.b64 {%0,%1}, %2;" : "=f"(lo), "=f"(hi) : "l"(v));
    return lo + hi;
}
__device__ __forceinline__ float tanh_(float x) {
    float r; asm("tanh.approx.f32 %0, %1;" : "=f"(r) : "f"(x)); return r;
}
__device__ __forceinline__ float sigm(float x) {
    return fmaf(tanh_(0.5f * x), 0.5f, 0.5f);
}

#define GRPBAR256(id) asm volatile("bar.sync %0, 256;" :: "r"(id) : "memory")

// GEMM over NKP k-pairs, NB rows. wrz = base + j*4 (stride 384), wn = +256+j*2.
// hb = h base (stride 28 floats/kp) + region offset. FULLY UNROLLED so all
// operand addresses fold to immediates off the base registers.
template<int NKP, int NB>
__device__ __forceinline__ void gemm_rzn(const float* __restrict__ wrz,
                                         const float* __restrict__ wn,
                                         const float* __restrict__ hb,
                                         u64 aR[NB], u64 aZ[NB], u64 aN[NB])
{
    #pragma unroll
    for (int kp = 0; kp < NKP; ++kp) {
        ulonglong2 wv = *(const ulonglong2*)(wrz + kp * 384);
        u64 wNv = *(const u64*)(wn + kp * 384);
        const float* hr = hb + kp * 28;
        u64 hv[NB];
        {
            ulonglong2 t0 = *(const ulonglong2*)(hr);
            ulonglong2 t1 = *(const ulonglong2*)(hr + 4);
            hv[0] = t0.x; hv[1] = t0.y; hv[2] = t1.x; hv[3] = t1.y;
            if constexpr (NB == 8) {
                ulonglong2 t2 = *(const ulonglong2*)(hr + 8);
                ulonglong2 t3 = *(const ulonglong2*)(hr + 12);
                hv[4] = t2.x; hv[5] = t2.y; hv[6] = t3.x; hv[7] = t3.y;
            } else {
                ulonglong2 t2 = *(const ulonglong2*)(hr + 8);
                hv[4] = t2.x; hv[5] = t2.y;
            }
        }
        #pragma unroll
        for (int b = 0; b < NB; ++b) {
            ffma2(aR[b], hv[b], wv.x);
            ffma2(aZ[b], hv[b], wv.y);
            ffma2(aN[b], hv[b], wNv);
        }
    }
}

struct Ctx {
    const float* xrow[4];              // t-invariant clamped x row pointers
    float* hp0; float* hp1;
    const float* w0rz; const float* w0n;
    const float* w1rz; const float* w1n;
    int ks, bgf, st0, bar_id;
    float wxr0, wxr1, wxz0, wxz1, wxn0, wxn1;
    float br0, bz0, bnx0, bnh0, br1, bz1, bnx1, bnh1;
};

template<int NB>
__device__ __forceinline__ void time_loop(const Ctx c, float* hprev0, float* hprev1)
{
    constexpr int F = NB / 2;
    const int ks = c.ks;
    for (int t = 0; t < TT; ++t) {
        const int cur = t & 1, nxt = cur ^ 1;
        float* hp0c = c.hp0 + cur * 896;
        float* hp0n = c.hp0 + nxt * 896;
        float* hp1c = c.hp1 + cur * 896;
        float* hp1n = c.hp1 + nxt * 896;

        // x(t) for my F finalized rows (pointers pre-clamped, t-invariant rows)
        const size_t toff = (size_t)t * (BB * 2);
        float xf[2 * F];
        #pragma unroll
        for (int i = 0; i < F; ++i) {
            float2 v = *(const float2*)(c.xrow[i] + toff);
            xf[2 * i] = v.x; xf[2 * i + 1] = v.y;
        }

        // ======== G0: layer-0 GEMM, my k-half over hp0[cur] ========
        u64 aR[NB], aZ[NB], aN[NB];
        #pragma unroll
        for (int b = 0; b < NB; ++b) { aR[b] = 0; aZ[b] = 0; aN[b] = 0; }
        gemm_rzn<16, NB>(c.w0rz, c.w0n, hp0c + ks * 448 + c.bgf, aR, aZ, aN);

        // ======== E0: k-split reduce + gates; write h0(t) -> hp0[nxt] ========
        #pragma unroll
        for (int i = 0; i < F; ++i) {
            u64 keepR = ks ? aR[F+i] : aR[i], sndR = ks ? aR[i] : aR[F+i];
            u64 keepZ = ks ? aZ[F+i] : aZ[i], sndZ = ks ? aZ[i] : aZ[F+i];
            u64 keepN = ks ? aN[F+i] : aN[i], sndN = ks ? aN[i] : aN[F+i];
            fadd2(keepR, __shfl_xor_sync(0xffffffffu, sndR, 16));
            fadd2(keepZ, __shfl_xor_sync(0xffffffffu, sndZ, 16));
            fadd2(keepN, __shfl_xor_sync(0xffffffffu, sndN, 16));
            float sR = fold(keepR), sZ = fold(keepZ), sN = fold(keepN);
            float x0 = xf[2*i], x1 = xf[2*i+1];
            float r = sigm(sR + x0 * c.wxr0 + x1 * c.wxr1 + c.br0);
            float z = sigm(sZ + x0 * c.wxz0 + x1 * c.wxz1 + c.bz0);
            float n = tanh_(x0 * c.wxn0 + x1 * c.wxn1 + c.bnx0 + r * (sN + c.bnh0));
            float h = n + z * (hprev0[i] - n);
            hprev0[i] = h;
            hp0n[c.st0 + i * 2] = h;
        }
        GRPBAR256(c.bar_id);   // h0(t) visible within group (only bar this step)

        // ==== G1: layer-1 GEMM. ks0: input side (Wih1) over hp0[nxt] (fresh h0);
        //          ks1: recurrent (Whh1) over hp1[cur]. 32 kp each. ====
        u64 cR[NB], cZ[NB], cN[NB];
        #pragma unroll
        for (int b = 0; b < NB; ++b) { cR[b] = 0; cZ[b] = 0; cN[b] = 0; }
        gemm_rzn<32, NB>(c.w1rz, c.w1n, (ks ? hp1c : hp0n) + c.bgf, cR, cZ, cN);

        // ======== E1: exchange + gates; write h1(t) -> hp1[nxt] ========
        #pragma unroll
        for (int i = 0; i < F; ++i) {
            u64 keepR = ks ? cR[F+i] : cR[i], sndR = ks ? cR[i] : cR[F+i];
            u64 keepZ = ks ? cZ[F+i] : cZ[i], sndZ = ks ? cZ[i] : cZ[F+i];
            u64 keepN = ks ? cN[F+i] : cN[i], sndN = ks ? cN[i] : cN[F+i];
            fadd2(keepR, __shfl_xor_sync(0xffffffffu, sndR, 16));
            fadd2(keepZ, __shfl_xor_sync(0xffffffffu, sndZ, 16));
            u64 rcvN = __shfl_xor_sync(0xffffffffu, sndN, 16);
            float sR = fold(keepR), sZ = fold(keepZ);
            float fm = fold(keepN), fr = fold(rcvN);
            float nx = ks ? fr : fm;      // input-side partial came from ks0
            float nh = ks ? fm : fr;      // recurrent partial came from ks1
            float r = sigm(sR + c.br1);
            float z = sigm(sZ + c.bz1);
            float n = tanh_(nx + c.bnx1 + r * (nh + c.bnh1));
            float h = n + z * (hprev1[i] - n);
            hprev1[i] = h;
            hp1n[c.st0 + i * 2] = h;
        }
        // no second barrier: next step's bar (after E0) orders E1 stores before
        // G1(t+1) reads hp1, and hp0[cur]'s reuse in E0(t+1) after G0(t)'s reads.
    }
}

extern "C" __global__ void __launch_bounds__(NTHR, 1)
gru2_kernel(const float* __restrict__ gx,
            const float* __restrict__ Wih0, const float* __restrict__ Whh0,
            const float* __restrict__ bih0, const float* __restrict__ bhh0,
            const float* __restrict__ Wih1, const float* __restrict__ Whh1,
            const float* __restrict__ bih1, const float* __restrict__ bhh1,
            const float* __restrict__ Wp,   const float* __restrict__ bp,
            float* __restrict__ out)
{
    extern __shared__ __align__(16) float sm[];
    const int tid = threadIdx.x;

    // ---- one-time weight staging (R6/R11 layout) ----
    for (int i = tid; i < 12288; i += NTHR) {
        int kp = i / 384, r = i % 384;
        float v;
        if (r < 256) {
            int j = r >> 2, sub = r & 3, gate = sub >> 1, e = sub & 1;
            v = Whh0[(gate * 64 + j) * 64 + 2 * kp + e];
        } else {
            int rr = r - 256, j = rr >> 1, e = rr & 1;
            v = Whh0[(128 + j) * 64 + 2 * kp + e];
        }
        sm[OFF_W0 + i] = v;
    }
    for (int i = tid; i < 24576; i += NTHR) {
        int kp = i / 384, r = i % 384;
        const float* W = (kp < 32) ? Wih1 : Whh1;
        int k0 = 2 * (kp & 31);
        float v;
        if (r < 256) {
            int j = r >> 2, sub = r & 3, gate = sub >> 1, e = sub & 1;
            v = W[(gate * 64 + j) * 64 + k0 + e];
        } else {
            int rr = r - 256, j = rr >> 1, e = rr & 1;
            v = W[(128 + j) * 64 + k0 + e];
        }
        sm[OFF_W1 + i] = v;
    }
    for (int i = tid; i < 2 * GRPH; i += NTHR) sm[OFF_H + i] = 0.0f;

    // ---- per-thread mapping ----
    const int warp   = tid >> 5;
    const int g      = tid >> 8;            // group 0/1 (warps 0-7 | 8-15)
    const int warp_g = warp & 7;
    const int jw     = warp_g & 3;          // 4 j-warps cover 64 j
    const int bg     = warp_g >> 2;         // region: 0 = 8 rows, 1 = 6 rows
    const int lane   = tid & 31;
    const int ks     = lane >> 4;
    const int jq     = lane & 15;
    const int j      = jw * 16 + jq;        // my j column (0..63)
    const int kpj    = j >> 1, ej = j & 1;
    const int F      = bg ? 3 : 4;
    const int lrow0  = bg * 8 + ks * F;     // first finalized local row (of 14)
    const int bglob  = blockIdx.x * 28 + g * 14 + lrow0;

    Ctx c;
    c.ks = ks;
    c.bgf = bg * 16;
    c.st0 = kpj * 28 + lrow0 * 2 + ej;
    c.bar_id = g + 1;

    // t-invariant clamped x row pointers
    #pragma unroll
    for (int i = 0; i < 4; ++i) {
        int br = bglob + i; if (br > BB - 1) br = BB - 1;
        c.xrow[i] = gx + (size_t)br * 2;
    }

    c.wxr0 = Wih0[j*2];        c.wxr1 = Wih0[j*2+1];
    c.wxz0 = Wih0[(64+j)*2];   c.wxz1 = Wih0[(64+j)*2+1];
    c.wxn0 = Wih0[(128+j)*2];  c.wxn1 = Wih0[(128+j)*2+1];
    c.br0 = bih0[j]    + bhh0[j];
    c.bz0 = bih0[64+j] + bhh0[64+j];
    c.bnx0 = bih0[128+j]; c.bnh0 = bhh0[128+j];
    c.br1 = bih1[j]    + bhh1[j];
    c.bz1 = bih1[64+j] + bhh1[64+j];
    c.bnx1 = bih1[128+j]; c.bnh1 = bhh1[128+j];

    c.w0rz = sm + OFF_W0 + (ks * 16) * 384 + j * 4;
    c.w0n  = sm + OFF_W0 + (ks * 16) * 384 + 256 + j * 2;
    c.w1rz = sm + OFF_W1 + (ks * 32) * 384 + j * 4;   // ks0: Wih1, ks1: Whh1
    c.w1n  = sm + OFF_W1 + (ks * 32) * 384 + 256 + j * 2;

    c.hp0 = sm + OFF_H + g * GRPH;          // 2 bufs x 896
    c.hp1 = c.hp0 + 1792;                   // 2 bufs x 896

    float hprev0[4] = {0.f, 0.f, 0.f, 0.f};
    float hprev1[4] = {0.f, 0.f, 0.f, 0.f};

    __syncthreads();

    if (bg == 0) time_loop<8>(c, hprev0, hprev1);
    else         time_loop<6>(c, hprev0, hprev1);

    // ---- projection: out[b] = sum_j Wp[j]*h0f[j] + Wp[64+j]*h1f[j] + bp ----
    __syncthreads();   // all groups done with h buffers
    {
        float* scr = sm + OFF_H;   // [28 rows][stride 68]
        const float wp0 = Wp[j], wp1 = Wp[64 + j];
        #pragma unroll
        for (int i = 0; i < 4; ++i) {
            if (i < F) {
                int lr = g * 14 + lrow0 + i;
                scr[lr * 68 + j] = wp0 * hprev0[i] + wp1 * hprev1[i];
            }
        }
        __syncthreads();
        if (tid < 28) {
            int rowg = blockIdx.x * 28 + tid;
            if (rowg < BB) {
                float s = bp[0];
                #pragma unroll 8
                for (int jj = 0; jj < 64; ++jj) s += scr[tid * 68 + jj];
                out[rowg] = s;
            }
        }
    }
}

extern "C" void kernel_launch(void* const* d_in, const int* in_sizes, int n_in,
                              void* d_out, int out_size)
{
    (void)in_sizes; (void)n_in; (void)out_size;
    const float* x    = (const float*)d_in[0];
    const float* Wih0 = (const float*)d_in[1];
    const float* Whh0 = (const float*)d_in[2];
    const float* bih0 = (const float*)d_in[3];
    const float* bhh0 = (const float*)d_in[4];
    const float* Wih1 = (const float*)d_in[5];
    const float* Whh1 = (const float*)d_in[6];
    const float* bih1 = (const float*)d_in[7];
    const float* bhh1 = (const float*)d_in[8];
    const float* Wp   = (const float*)d_in[9];
    const float* bp   = (const float*)d_in[10];
    float* out = (float*)d_out;

    cudaFuncSetAttribute(gru2_kernel, cudaFuncAttributeMaxDynamicSharedMemorySize, SMEM_BYTES);
    gru2_kernel<<<NBLK, NTHR, SMEM_BYTES>>>(x, Wih0, Whh0, bih0, bhh0,
                                            Wih1, Whh1, bih1, bhh1, Wp, bp, out);
}